// round 7
// baseline (speedup 1.0000x reference)
#include <cuda_runtime.h>

typedef unsigned int u32;

#define HID        50
#define ROW_W      16                       // padded words per weight row (16B-aligned uint4 loads)
#define W1_BASE    0                        // 50 words (+pad to 64)
#define HID_BASE   64
#define HID_STRIDE (HID * ROW_W)            // 800 words per hidden layer
#define WO_BASE    (HID_BASE + 3 * HID_STRIDE)   // 2464
#define SC_BASE    (WO_BASE + 2 * ROW_W)         // 2496
#define PACK_WORDS (SC_BASE + 8)                 // 2504 words ~= 10 KB

#define TBL_DIM    255
#define TBL_SIZE   (TBL_DIM * TBL_DIM)      // 65025

#define MAGIC_F 12582912.0f                 // 1.5 * 2^23
#define MAGIC_I 0x4B400000

__device__ unsigned int g_absmax_bits = 0u;
__device__ u32          g_packed[PACK_WORDS];
__device__ float2       g_table[TBL_SIZE];

// ---------------------------------------------------------------------------
// K1: max(|z|,|t|) over all samples -> g_absmax_bits (positive-float bit trick)
// ---------------------------------------------------------------------------
__global__ void absmax_kernel(const float* __restrict__ z,
                              const float* __restrict__ t, int n) {
    int i = blockIdx.x * blockDim.x + threadIdx.x;
    int stride = gridDim.x * blockDim.x;
    float m = 0.0f;
    for (; i < n; i += stride)
        m = fmaxf(m, fmaxf(fabsf(z[i]), fabsf(t[i])));
#pragma unroll
    for (int o = 16; o > 0; o >>= 1)
        m = fmaxf(m, __shfl_xor_sync(0xFFFFFFFFu, m, o));
    if ((threadIdx.x & 31) == 0)
        atomicMax(&g_absmax_bits, __float_as_uint(m));
}

// round-half-even then clip to +/-127 (matches jnp: clip(round(x), -127, 127))
__device__ __forceinline__ int q8(float x) {
    float r = rintf(x);
    r = fminf(fmaxf(r, -127.0f), 127.0f);
    return (int)r;
}

// ---------------------------------------------------------------------------
// K2: weight scales + int8 packing.
// Row layout (13 words, padded to 16): word w holds neurons' weights for
// k = 4w..4w+3 as signed bytes; word 12 byte2 holds the int8 bias (paired with
// a constant 1 in activation byte 50). Also resets g_absmax_bits for replay.
// ---------------------------------------------------------------------------
__global__ void prep_kernel(const float* __restrict__ W1, const float* __restrict__ b1,
                            const float* __restrict__ W2, const float* __restrict__ b2,
                            const float* __restrict__ W3, const float* __restrict__ b3,
                            const float* __restrict__ W4, const float* __restrict__ b4,
                            const float* __restrict__ Wo, const float* __restrict__ bo) {
    __shared__ float red[256];
    __shared__ float wsc[5];
    int tid = threadIdx.x;

    float in_max  = fmaxf(__uint_as_float(g_absmax_bits), 1e-8f);
    float in_scale = in_max / 127.0f;

    const float* Ws[5]  = {W1, W2, W3, W4, Wo};
    const int    szs[5] = {100, 2500, 2500, 2500, 100};
    for (int tw = 0; tw < 5; ++tw) {
        float m = 0.0f;
        for (int i = tid; i < szs[tw]; i += 256) m = fmaxf(m, fabsf(Ws[tw][i]));
        red[tid] = m;
        __syncthreads();
        for (int s = 128; s > 0; s >>= 1) {
            if (tid < s) red[tid] = fmaxf(red[tid], red[tid + s]);
            __syncthreads();
        }
        if (tid == 0) wsc[tw] = fmaxf(red[0], 1e-8f) / 127.0f;
        __syncthreads();
    }

    // Layer 1 (fan_in=2): word = (q0, q1, b_int, 0) per neuron
    if (tid < HID) {
        float ws  = wsc[0];
        float bsc = in_scale * ws;
        int q0 = q8(W1[tid * 2 + 0] / ws);
        int q1 = q8(W1[tid * 2 + 1] / ws);
        int bi = q8(b1[tid] / bsc);
        g_packed[W1_BASE + tid] = (u32)(q0 & 0xFF) | ((u32)(q1 & 0xFF) << 8) |
                                  ((u32)(bi & 0xFF) << 16);
    }
    if (tid >= HID && tid < HID_BASE) g_packed[tid] = 0;

    const float* Wh[3] = {W2, W3, W4};
    const float* bh[3] = {b2, b3, b4};
    if (tid < HID) {
        for (int l = 0; l < 3; ++l) {
            float ws  = wsc[1 + l];
            float bsc = (1.0f / 127.0f) * ws;       // ACT_SCALE * w_scale
            int bi = q8(bh[l][tid] / bsc);
            const float* Wr = Wh[l] + tid * HID;
            u32* dst = &g_packed[HID_BASE + l * HID_STRIDE + tid * ROW_W];
            for (int w = 0; w < 13; ++w) {
                u32 word = 0;
                for (int e = 0; e < 4; ++e) {
                    int k = 4 * w + e;
                    int q = (k < HID) ? q8(Wr[k] / ws) : 0;
                    if (w == 12 && e == 2) q = bi;
                    word |= (u32)(q & 0xFF) << (8 * e);
                }
                dst[w] = word;
            }
            dst[13] = 0; dst[14] = 0; dst[15] = 0;
        }
    }

    if (tid < 2) {
        float ws  = wsc[4];
        float bsc = (1.0f / 127.0f) * ws;
        int bi = q8(bo[tid] / bsc);
        const float* Wr = Wo + tid * HID;
        u32* dst = &g_packed[WO_BASE + tid * ROW_W];
        for (int w = 0; w < 13; ++w) {
            u32 word = 0;
            for (int e = 0; e < 4; ++e) {
                int k = 4 * w + e;
                int q = (k < HID) ? q8(Wr[k] / ws) : 0;
                if (w == 12 && e == 2) q = bi;
                word |= (u32)(q & 0xFF) << (8 * e);
            }
            dst[w] = word;
        }
        dst[13] = 0; dst[14] = 0; dst[15] = 0;
    }

    if (tid == 0) {
        g_packed[SC_BASE + 0] = __float_as_uint(in_scale);
        g_packed[SC_BASE + 1] = __float_as_uint(in_scale * wsc[0] * 127.0f); // L1: h*127 = acc*S1
        g_packed[SC_BASE + 2] = __float_as_uint(wsc[1]);                     // hidden: h*127 = acc*ws
        g_packed[SC_BASE + 3] = __float_as_uint(wsc[2]);
        g_packed[SC_BASE + 4] = __float_as_uint(wsc[3]);
        g_packed[SC_BASE + 5] = __float_as_uint((1.0f / 127.0f) * wsc[4]);   // out = acc*So
        g_packed[SC_BASE + 6] = 0; g_packed[SC_BASE + 7] = 0;
        g_absmax_bits = 0u;  // reset for next graph replay (deterministic)
    }
}

// ---------------------------------------------------------------------------
// MLP core (int8 dp4a, exact int32 accumulation)
// ---------------------------------------------------------------------------
__device__ __forceinline__ u32 pack4(u32 u0, u32 u1, u32 u2, u32 u3) {
    return __byte_perm(__byte_perm(u0, u1, 0x0040),
                       __byte_perm(u2, u3, 0x0040), 0x5410);
}

// quantize pre-activation: k = clamp(rne(acc*scale), -127, 127); returns float
// bits of MAGIC+k (low byte = two's-complement int8 k)
__device__ __forceinline__ u32 quant_act(int acc, float scale) {
    float accf = __int_as_float(MAGIC_I + acc) - MAGIC_F;  // exact int->float
    float v = accf * scale;                                // single rounding
    v = fminf(fmaxf(v, -127.0f), 127.0f);
    return __float_as_uint(v + MAGIC_F);                   // rne in low bits
}

__device__ __forceinline__ void hidden_layer(const u32* __restrict__ sw,
                                             const u32 ain[13], u32 aout[13],
                                             float scale) {
#pragma unroll
    for (int jw = 0; jw < 13; ++jw) {
        const int nj = (jw == 12) ? 2 : 4;
        u32 u[4];
#pragma unroll
        for (int r = 0; r < nj; ++r) {
            const u32* wr = sw + (jw * 4 + r) * ROW_W;
            uint4 w0 = *reinterpret_cast<const uint4*>(wr);
            uint4 w1 = *reinterpret_cast<const uint4*>(wr + 4);
            uint4 w2 = *reinterpret_cast<const uint4*>(wr + 8);
            u32   wl = wr[12];
            int acc = 0;
            acc = __dp4a((int)ain[0],  (int)w0.x, acc);
            acc = __dp4a((int)ain[1],  (int)w0.y, acc);
            acc = __dp4a((int)ain[2],  (int)w0.z, acc);
            acc = __dp4a((int)ain[3],  (int)w0.w, acc);
            acc = __dp4a((int)ain[4],  (int)w1.x, acc);
            acc = __dp4a((int)ain[5],  (int)w1.y, acc);
            acc = __dp4a((int)ain[6],  (int)w1.z, acc);
            acc = __dp4a((int)ain[7],  (int)w1.w, acc);
            acc = __dp4a((int)ain[8],  (int)w2.x, acc);
            acc = __dp4a((int)ain[9],  (int)w2.y, acc);
            acc = __dp4a((int)ain[10], (int)w2.z, acc);
            acc = __dp4a((int)ain[11], (int)w2.w, acc);
            acc = __dp4a((int)ain[12], (int)wl,   acc);
            u[r] = quant_act(acc, scale);
        }
        if (jw < 12)
            aout[jw] = pack4(u[0], u[1], u[2], u[3]);
        else  // neurons 48,49 + constant-1 byte (bias lane) + zero pad
            aout[12] = (__byte_perm(u[0], u[1], 0x0040) & 0xFFFFu) | 0x00010000u;
    }
}

// ---------------------------------------------------------------------------
// K3: build the 255x255 output table. One thread = one (kz, kt) cell.
// ---------------------------------------------------------------------------
__global__ void __launch_bounds__(256) table_kernel() {
    __shared__ __align__(16) u32 sBuf[PACK_WORDS];
    for (int w = threadIdx.x; w < PACK_WORDS; w += blockDim.x)
        sBuf[w] = g_packed[w];
    __syncthreads();

    int idx = blockIdx.x * blockDim.x + threadIdx.x;
    if (idx >= TBL_SIZE) return;
    int kz = idx / TBL_DIM - 127;
    int kt = idx % TBL_DIM - 127;
    u32 a0 = (u32)(kz & 0xFF) | ((u32)(kt & 0xFF) << 8) | 0x00010000u;

    u32 hA[13], hB[13];

    // Layer 1
    {
        float S1 = __uint_as_float(sBuf[SC_BASE + 1]);
#pragma unroll
        for (int jw = 0; jw < 13; ++jw) {
            const int nj = (jw == 12) ? 2 : 4;
            u32 wv[4];
            if (jw < 12) {
                uint4 w4 = *reinterpret_cast<const uint4*>(&sBuf[W1_BASE + jw * 4]);
                wv[0] = w4.x; wv[1] = w4.y; wv[2] = w4.z; wv[3] = w4.w;
            } else {
                uint2 w2v = *reinterpret_cast<const uint2*>(&sBuf[W1_BASE + 48]);
                wv[0] = w2v.x; wv[1] = w2v.y;
            }
            u32 u[4];
#pragma unroll
            for (int r = 0; r < nj; ++r) {
                int acc = __dp4a((int)a0, (int)wv[r], 0);
                u[r] = quant_act(acc, S1);
            }
            if (jw < 12) hA[jw] = pack4(u[0], u[1], u[2], u[3]);
            else         hA[12] = (__byte_perm(u[0], u[1], 0x0040) & 0xFFFFu) | 0x00010000u;
        }
    }

    hidden_layer(&sBuf[HID_BASE + 0 * HID_STRIDE], hA, hB, __uint_as_float(sBuf[SC_BASE + 2]));
    hidden_layer(&sBuf[HID_BASE + 1 * HID_STRIDE], hB, hA, __uint_as_float(sBuf[SC_BASE + 3]));
    hidden_layer(&sBuf[HID_BASE + 2 * HID_STRIDE], hA, hB, __uint_as_float(sBuf[SC_BASE + 4]));

    // Output layer (2 neurons)
    float So = __uint_as_float(sBuf[SC_BASE + 5]);
    const u32* w0r = &sBuf[WO_BASE];
    const u32* w1r = &sBuf[WO_BASE + ROW_W];
    int acc0 = 0, acc1 = 0;
#pragma unroll
    for (int k = 0; k < 13; ++k) {
        acc0 = __dp4a((int)hB[k], (int)w0r[k], acc0);
        acc1 = __dp4a((int)hB[k], (int)w1r[k], acc1);
    }
    float a0f = __int_as_float(MAGIC_I + acc0) - MAGIC_F;
    float a1f = __int_as_float(MAGIC_I + acc1) - MAGIC_F;
    g_table[idx] = make_float2(a0f * So, a1f * So);
}

// ---------------------------------------------------------------------------
// K4: per-sample quantize + table gather
// ---------------------------------------------------------------------------
__global__ void __launch_bounds__(256) gather_kernel(const float* __restrict__ z,
                                                     const float* __restrict__ t,
                                                     float* __restrict__ out, int n) {
    int i = blockIdx.x * blockDim.x + threadIdx.x;
    if (i >= n) return;
    float in_scale = __uint_as_float(g_packed[SC_BASE + 0]);
    float zq = fminf(fmaxf(rintf(z[i] / in_scale), -127.0f), 127.0f);
    float tq = fminf(fmaxf(rintf(t[i] / in_scale), -127.0f), 127.0f);
    int idx = ((int)zq + 127) * TBL_DIM + ((int)tq + 127);
    reinterpret_cast<float2*>(out)[i] = g_table[idx];
}

// ---------------------------------------------------------------------------
extern "C" void kernel_launch(void* const* d_in, const int* in_sizes, int n_in,
                              void* d_out, int out_size) {
    const float* z  = (const float*)d_in[0];
    const float* t  = (const float*)d_in[1];
    const float* W1 = (const float*)d_in[2];
    const float* b1 = (const float*)d_in[3];
    const float* W2 = (const float*)d_in[4];
    const float* b2 = (const float*)d_in[5];
    const float* W3 = (const float*)d_in[6];
    const float* b3 = (const float*)d_in[7];
    const float* W4 = (const float*)d_in[8];
    const float* b4 = (const float*)d_in[9];
    const float* Wo = (const float*)d_in[10];
    const float* bo = (const float*)d_in[11];
    int n = in_sizes[0];

    absmax_kernel<<<256, 256>>>(z, t, n);
    prep_kernel<<<1, 256>>>(W1, b1, W2, b2, W3, b3, W4, b4, Wo, bo);
    table_kernel<<<(TBL_SIZE + 255) / 256, 256>>>();
    gather_kernel<<<(n + 255) / 256, 256>>>(z, t, (float*)d_out, n);
}